// round 15
// baseline (speedup 1.0000x reference)
#include <cuda_runtime.h>
#include <cuda_fp16.h>
#include <cstdint>

#define Bc  2
#define Sc  2048
#define Dc  1024
#define Hc  16
#define DHc 64
#define Mrows (Bc*Sc)          // 4096
typedef __half fp16;

// ---------------- device scratch (no allocation allowed) ----------------
__device__ fp16 g_xh [Mrows*Dc];                        // x hi
__device__ fp16 g_Wh [4*Dc*Dc];                         // W^T hi, [n][k]
__device__ fp16 g_Qh [Bc*Hc*Sc*DHc];                    // Q hi (scale folded in)
__device__ fp16 g_Kh [Bc*Hc*Sc*DHc];                    // K hi
__device__ fp16 g_Vh [Bc*Hc*Sc*DHc];                    // V hi
__device__ fp16 g_AOh[Mrows*Dc];                        // AO hi
__device__ int  g_tick;
__device__ int  g_done[32];                             // per-(b,qt) head count

#define SCALE_L2E 0.18033688f   // 0.125 * log2(e), folded into Q

// ---------------- helpers ----------------
__device__ __forceinline__ uint32_t smem_u32(const void* p) {
    uint32_t a;
    asm("{ .reg .u64 t; cvta.to.shared.u64 t, %1; cvt.u32.u64 %0, t; }" : "=r"(a) : "l"(p));
    return a;
}
__device__ __forceinline__ void ldsm4(uint32_t* r, uint32_t addr) {
    asm volatile("ldmatrix.sync.aligned.m8n8.x4.shared.b16 {%0,%1,%2,%3}, [%4];"
        : "=r"(r[0]), "=r"(r[1]), "=r"(r[2]), "=r"(r[3]) : "r"(addr));
}
__device__ __forceinline__ void ldsm4t(uint32_t* r, uint32_t addr) {
    asm volatile("ldmatrix.sync.aligned.m8n8.x4.trans.shared.b16 {%0,%1,%2,%3}, [%4];"
        : "=r"(r[0]), "=r"(r[1]), "=r"(r[2]), "=r"(r[3]) : "r"(addr));
}
__device__ __forceinline__ void mma16816(float* d, const uint32_t* a,
                                         uint32_t b0, uint32_t b1) {
    asm volatile("mma.sync.aligned.m16n8k16.row.col.f32.f16.f16.f32 "
        "{%0,%1,%2,%3}, {%4,%5,%6,%7}, {%8,%9}, {%0,%1,%2,%3};"
        : "+f"(d[0]), "+f"(d[1]), "+f"(d[2]), "+f"(d[3])
        : "r"(a[0]), "r"(a[1]), "r"(a[2]), "r"(a[3]), "r"(b0), "r"(b1));
}
__device__ __forceinline__ uint32_t pack2h(float x, float y) {
    __half2 h = __floats2half2_rn(x, y);
    return *(uint32_t*)&h;
}
__device__ __forceinline__ float ex2f(float x) {
    float y;
    asm("ex2.approx.f32 %0, %1;" : "=f"(y) : "f"(x));
    return y;
}
__device__ __forceinline__ uint32_t hmax2(uint32_t a, uint32_t b) {
    uint32_t d;
    asm("max.f16x2 %0, %1, %2;" : "=r"(d) : "r"(a), "r"(b));
    return d;
}
__device__ __forceinline__ uint32_t hsub2(uint32_t a, uint32_t b) {
    uint32_t d;
    asm("sub.f16x2 %0, %1, %2;" : "=r"(d) : "r"(a), "r"(b));
    return d;
}
__device__ __forceinline__ uint32_t hex2(uint32_t a) {
    uint32_t d;
    asm("ex2.approx.f16x2 %0, %1;" : "=r"(d) : "r"(a));
    return d;
}
__device__ __forceinline__ void cpa16(uint32_t s, const void* g) {
    asm volatile("cp.async.cg.shared.global [%0], [%1], 16;" :: "r"(s), "l"(g));
}
__device__ __forceinline__ void cpa_commit() {
    asm volatile("cp.async.commit_group;" ::: "memory");
}
template<int N>
__device__ __forceinline__ void cpa_wait() {
    asm volatile("cp.async.wait_group %0;" :: "n"(N) : "memory");
}

// ---------------- prep: fused x-convert + 4 weight transposes ----------------
__global__ void prep_kernel(const float* __restrict__ x,
                            const float* __restrict__ Wq,
                            const float* __restrict__ Wk,
                            const float* __restrict__ Wv,
                            const float* __restrict__ Wo)
{
    if (blockIdx.z == 4) {
        const int blk = blockIdx.y * 32 + blockIdx.x;
        const int t = threadIdx.y * 32 + threadIdx.x;
        if (blk == 0 && t == 0) {
            g_tick = 0;
#pragma unroll
            for (int i = 0; i < 32; i++) g_done[i] = 0;
        }
        size_t i = ((size_t)blk * 256 + t) * 16;
#pragma unroll
        for (int j = 0; j < 2; j++) {
            float4 v0 = *(const float4*)(x + i + j * 8);
            float4 v1 = *(const float4*)(x + i + j * 8 + 4);
            uint4 o;
            o.x = pack2h(v0.x, v0.y); o.y = pack2h(v0.z, v0.w);
            o.z = pack2h(v1.x, v1.y); o.w = pack2h(v1.z, v1.w);
            *(uint4*)(g_xh + i + j * 8) = o;
        }
        return;
    }
    __shared__ float t[32][33];
    const int wsel = blockIdx.z;
    const float* src = (wsel == 0) ? Wq : (wsel == 1) ? Wk : (wsel == 2) ? Wv : Wo;
    fp16* dh = g_Wh + (size_t)wsel * Dc * Dc;
    int x0 = blockIdx.x * 32 + threadIdx.x;
    int y0 = blockIdx.y * 32 + threadIdx.y;
#pragma unroll
    for (int i = 0; i < 32; i += 8) t[threadIdx.y + i][threadIdx.x] = src[(y0 + i) * Dc + x0];
    __syncthreads();
    x0 = blockIdx.y * 32 + threadIdx.x;
    y0 = blockIdx.x * 32 + threadIdx.y;
#pragma unroll
    for (int i = 0; i < 32; i += 8)
        dh[(size_t)(y0 + i) * Dc + x0] = __float2half_rn(t[threadIdx.x][threadIdx.y + i]);
}

// ---------------------------------------------------------------------------
// fp16 1-term QKV GEMM (R13 config): tile 128x128, BK=32, 256 thr,
// cp.async 4-stage x 2-tile pipeline, 2 CTAs/SM. grid (24,32).
// ---------------------------------------------------------------------------
#define GT_TILE  10240u    // 128*40*2
#define GT_STAGE 20480u    // 2 tiles
#define GT_NST   4

__global__ __launch_bounds__(256, 2)
void gemm_qkv(const float* __restrict__ b0, const float* __restrict__ b1,
              const float* __restrict__ b2)
{
    extern __shared__ unsigned char smraw[];
    const uint32_t sb = smem_u32(smraw);
    const int tid = threadIdx.x;
    const int wid = tid >> 5, lid = tid & 31;
    const int wr = wid >> 2, wc = wid & 3;
    const int m0 = blockIdx.y * 128;

    const int wsel = blockIdx.x >> 3;
    const int n0 = (blockIdx.x & 7) * 128;
    const fp16* Ah_ = g_xh;
    const fp16* Bh_ = g_Wh + (size_t)wsel * Dc * Dc;
    const float* bias = (wsel == 0) ? b0 : (wsel == 1) ? b1 : b2;

    auto issue = [&](int c, int st) {
#pragma unroll
        for (int j = 0; j < 4; j++) {
            const int tile = j >> 1;
            const int idx = (j & 1) * 256 + tid;
            const int row = idx >> 2, ch = idx & 3;
            const fp16* g = (tile == 0)
                ? Ah_ + (size_t)(m0 + row) * Dc + c * 32 + ch * 8
                : Bh_ + (size_t)(n0 + row) * Dc + c * 32 + ch * 8;
            cpa16(sb + (uint32_t)st * GT_STAGE +
                  (uint32_t)(tile * (int)GT_TILE + row * 80 + ch * 16), g);
        }
        cpa_commit();
    };

    float acc[4][4][4];
#pragma unroll
    for (int mt = 0; mt < 4; mt++)
#pragma unroll
        for (int nt = 0; nt < 4; nt++)
#pragma unroll
            for (int e = 0; e < 4; e++) acc[mt][nt][e] = 0.f;

#pragma unroll
    for (int s = 0; s < GT_NST - 1; s++) issue(s, s);

    const int lrow = lid & 15;
    const int lko  = (lid >> 4) << 3;

    for (int c = 0; c < 32; c++) {
        const int rem = 31 - c;
        if (rem >= GT_NST - 2)  { cpa_wait<GT_NST - 2>(); }
        else if (rem == 1)      { cpa_wait<1>(); }
        else                    { cpa_wait<0>(); }
        __syncthreads();
        if (c + GT_NST - 1 < 32) issue(c + GT_NST - 1, (c + GT_NST - 1) & (GT_NST - 1));

        const uint32_t base = sb + (uint32_t)(c & (GT_NST - 1)) * GT_STAGE;
#pragma unroll
        for (int ks = 0; ks < 2; ks++) {
            const uint32_t lk = (uint32_t)(ks * 16 + lko);
            uint32_t af[4][4], bf2[2][4];
#pragma unroll
            for (int mt = 0; mt < 4; mt++) {
                uint32_t ad = base + ((uint32_t)(wr * 64 + mt * 16 + lrow) * 40u + lk) * 2u;
                ldsm4(af[mt], ad);
            }
#pragma unroll
            for (int nt2 = 0; nt2 < 2; nt2++) {
                uint32_t bd = base + GT_TILE +
                              ((uint32_t)(wc * 32 + nt2 * 16 + lrow) * 40u + lk) * 2u;
                ldsm4(bf2[nt2], bd);
            }
#pragma unroll
            for (int mt = 0; mt < 4; mt++)
#pragma unroll
                for (int n8 = 0; n8 < 4; n8++) {
                    const int nt2 = n8 >> 1, sel = n8 & 1;
                    mma16816(acc[mt][n8], af[mt], bf2[nt2][sel], bf2[nt2][sel + 2]);
                }
        }
    }

    const int gid = lid >> 2, tig = lid & 3;
#pragma unroll
    for (int mt = 0; mt < 4; mt++) {
#pragma unroll
        for (int nt = 0; nt < 4; nt++) {
            int row = m0 + wr * 64 + mt * 16 + gid;
            int col = n0 + wc * 32 + nt * 8 + tig * 2;
            float bx = bias[col], by = bias[col + 1];
            float v00 = acc[mt][nt][0] + bx, v01 = acc[mt][nt][1] + by;
            float v10 = acc[mt][nt][2] + bx, v11 = acc[mt][nt][3] + by;
            int h = col >> 6, dh = col & 63;
            int bb = row >> 11, s = row & (Sc - 1);
            size_t p0 = ((size_t)(bb * Hc + h) * Sc + s) * DHc + dh;
            size_t p1 = ((size_t)(bb * Hc + h) * Sc + (s + 8)) * DHc + dh;
            if (wsel == 0) {
                *(uint32_t*)(g_Qh + p0) = pack2h(v00 * SCALE_L2E, v01 * SCALE_L2E);
                *(uint32_t*)(g_Qh + p1) = pack2h(v10 * SCALE_L2E, v11 * SCALE_L2E);
            } else {
                fp16* Oh = (wsel == 1) ? g_Kh : g_Vh;
                *(uint32_t*)(Oh + p0) = pack2h(v00, v01);
                *(uint32_t*)(Oh + p1) = pack2h(v10, v11);
            }
        }
    }
}

// ---------------------------------------------------------------------------
// Fused persistent kernel: tickets 0..511 = attention items (R13 config:
// q-tile 128, LPT), tickets 512..767 = out-projection tiles (128x128,
// dependency-gated on per-(b,qt) counters, qt-descending order).
// 152 CTAs x 256 thr, 1 CTA/SM. smem 92160B (union of both layouts).
// ---------------------------------------------------------------------------
#define AT_STRIDE 72u
#define AT_TILE   18432u   // 128*72*2
#define N_ATTN    512
#define N_TOTAL   768

__global__ __launch_bounds__(256, 1)
void fused_attn_out(const float* __restrict__ bo, float* __restrict__ outf)
{
    extern __shared__ unsigned char smraw[];
    __shared__ int s_item;
    const uint32_t sb = smem_u32(smraw);

    const int tid = threadIdx.x;
    const int wid = tid >> 5, lid = tid & 31;
    const int gid = lid >> 2, tig = lid & 3;
    const int lrow = lid & 15, lko = (lid >> 4) << 3;
    const uint32_t s_one = (lid < 4) ? 0x3C003C00u : 0u;   // ones col-0 B frag

    for (;;) {
        if (tid == 0) s_item = atomicAdd(&g_tick, 1);
        __syncthreads();
        const int item = s_item;
        if (item >= N_TOTAL) return;

        if (item < N_ATTN) {
            // ================= attention item =================
            const int qt = 15 - (item >> 5);     // heavy first (LPT)
            const int bh = item & 31;
            const int q0 = qt * 128;
            const size_t hb = (size_t)bh * (Sc * DHc);

            auto issue_kv = [&](int kt, int buf) {
                const uint32_t bbase = sb + (uint32_t)buf * (2u * AT_TILE);
                const int k0 = kt * 128;
#pragma unroll
                for (int j = 0; j < 8; j++) {
                    const int tile = j >> 2;          // 0 Kh, 1 Vh
                    const int idx = (j & 3) * 256 + tid;
                    const int row = idx >> 3, ch = idx & 7;
                    const fp16* g = (tile == 0 ? g_Kh : g_Vh) + hb +
                                    (size_t)(k0 + row) * DHc + ch * 8;
                    cpa16(bbase + (uint32_t)(tile * (int)AT_TILE + row * 144 + ch * 16), g);
                }
                cpa_commit();
            };

            // stage Q (group 1), prefetch KV0 (group 2)
#pragma unroll
            for (int j = 0; j < 4; j++) {
                const int idx = j * 256 + tid;
                const int row = idx >> 3, ch = idx & 7;
                const fp16* g = g_Qh + hb + (size_t)(q0 + row) * DHc + ch * 8;
                cpa16(sb + (uint32_t)(4 * (int)AT_TILE + row * 144 + ch * 16), g);
            }
            cpa_commit();
            issue_kv(0, 0);
            cpa_wait<1>();
            __syncthreads();

            uint32_t qh[4][4];
#pragma unroll
            for (int ks = 0; ks < 4; ks++) {
                uint32_t ad = sb + 4u * AT_TILE +
                              ((uint32_t)(wid * 16 + lrow) * AT_STRIDE +
                               (uint32_t)(ks * 16 + lko)) * 2u;
                ldsm4(qh[ks], ad);
            }

            float m_i[2] = {-1e30f, -1e30f}, l_i[2] = {0.f, 0.f};
            float oacc[8][4];
#pragma unroll
            for (int n8 = 0; n8 < 8; n8++)
#pragma unroll
                for (int e = 0; e < 4; e++) oacc[n8][e] = 0.f;

            for (int kt = 0; kt <= qt; kt++) {
                cpa_wait<0>();
                __syncthreads();
                if (kt < qt) issue_kv(kt + 1, (kt + 1) & 1);

                const uint32_t bbuf = sb + (uint32_t)(kt & 1) * (2u * AT_TILE);

                float sacc[16][4];
#pragma unroll
                for (int j = 0; j < 16; j++)
#pragma unroll
                    for (int e = 0; e < 4; e++) sacc[j][e] = 0.f;

#pragma unroll
                for (int ks = 0; ks < 4; ks++) {
#pragma unroll
                    for (int nt2 = 0; nt2 < 8; nt2++) {
                        uint32_t bh4[4];
                        uint32_t bd = bbuf + ((uint32_t)(nt2 * 16 + lrow) * AT_STRIDE +
                                              (uint32_t)(ks * 16 + lko)) * 2u;
                        ldsm4(bh4, bd);
#pragma unroll
                        for (int sel = 0; sel < 2; sel++)
                            mma16816(sacc[nt2 * 2 + sel], qh[ks], bh4[sel], bh4[sel + 2]);
                    }
                }

                if (kt == qt) {
#pragma unroll
                    for (int j = 0; j < 16; j++)
#pragma unroll
                        for (int e = 0; e < 4; e++) {
                            int row = wid * 16 + gid + ((e >> 1) << 3);
                            int col = j * 8 + tig * 2 + (e & 1);
                            if (col > row) sacc[j][e] = -1e30f;
                        }
                }

                uint32_t h0[16], h1[16];
#pragma unroll
                for (int j = 0; j < 16; j++) {
                    h0[j] = pack2h(sacc[j][0], sacc[j][1]);
                    h1[j] = pack2h(sacc[j][2], sacc[j][3]);
                }

                float corr[2];
#pragma unroll
                for (int hrow = 0; hrow < 2; hrow++) {
                    uint32_t* hx = hrow ? h1 : h0;
                    uint32_t m2 = hx[0];
#pragma unroll
                    for (int j = 1; j < 16; j++) m2 = hmax2(m2, hx[j]);
                    __half2 hm = *(__half2*)&m2;
                    float mxf = fmaxf(__half2float(__low2half(hm)),
                                      __half2float(__high2half(hm)));
                    mxf = fmaxf(mxf, __shfl_xor_sync(0xffffffffu, mxf, 1));
                    mxf = fmaxf(mxf, __shfl_xor_sync(0xffffffffu, mxf, 2));
                    float mnew = fmaxf(m_i[hrow], mxf);
                    corr[hrow] = ex2f(m_i[hrow] - mnew);
                    m_i[hrow] = mnew;
                    const uint32_t mn2 = pack2h(mnew, mnew);
#pragma unroll
                    for (int j = 0; j < 16; j++) hx[j] = hex2(hsub2(hx[j], mn2));
                    const int e0 = hrow * 2;
#pragma unroll
                    for (int n8 = 0; n8 < 8; n8++) {
                        oacc[n8][e0]     *= corr[hrow];
                        oacc[n8][e0 + 1] *= corr[hrow];
                    }
                }

                float lacc[4] = {0.f, 0.f, 0.f, 0.f};
#pragma unroll
                for (int ks2 = 0; ks2 < 8; ks2++) {
                    uint32_t pa[4];
                    pa[0] = h0[2 * ks2];     pa[1] = h1[2 * ks2];
                    pa[2] = h0[2 * ks2 + 1]; pa[3] = h1[2 * ks2 + 1];

                    mma16816(lacc, pa, s_one, s_one);

                    const int mat = lid >> 3, rin = lid & 7;
                    const uint32_t vrow = (uint32_t)(ks2 * 16 + (mat & 1) * 8 + rin);
#pragma unroll
                    for (int n2 = 0; n2 < 4; n2++) {
                        uint32_t vh4[4];
                        uint32_t vd = bbuf + AT_TILE +
                                      (vrow * AT_STRIDE +
                                       (uint32_t)(n2 * 16 + (mat >> 1) * 8)) * 2u;
                        ldsm4t(vh4, vd);
#pragma unroll
                        for (int sel = 0; sel < 2; sel++)
                            mma16816(oacc[n2 * 2 + sel], pa, vh4[sel * 2], vh4[sel * 2 + 1]);
                    }
                }

                const int src = (lid >> 2) << 2;
                float rs0 = __shfl_sync(0xffffffffu, lacc[0], src);
                float rs1 = __shfl_sync(0xffffffffu, lacc[2], src);
                l_i[0] = l_i[0] * corr[0] + rs0;
                l_i[1] = l_i[1] * corr[1] + rs1;
            }

            // epilogue: normalize + write AO hi (fp16)
            const int b = bh >> 4, h = bh & 15;
            const float inv0 = 1.f / l_i[0], inv1 = 1.f / l_i[1];
            const int row0 = q0 + wid * 16 + gid;
#pragma unroll
            for (int n8 = 0; n8 < 8; n8++) {
                const int col = h * DHc + n8 * 8 + tig * 2;
                size_t p0 = ((size_t)b * Sc + row0) * Dc + col;
                size_t p1 = ((size_t)b * Sc + row0 + 8) * Dc + col;
                *(uint32_t*)(g_AOh + p0) = pack2h(oacc[n8][0] * inv0, oacc[n8][1] * inv0);
                *(uint32_t*)(g_AOh + p1) = pack2h(oacc[n8][2] * inv1, oacc[n8][3] * inv1);
            }

            // signal completion of this (b, qt) head slice
            __threadfence();
            __syncthreads();
            if (tid == 0) atomicAdd(&g_done[b * 16 + qt], 1);

        } else {
            // ================= out-projection tile =================
            const int t = item - N_ATTN;          // 0..255
            const int nb = t & 7;                 // n-block (8 of 128)
            const int tq = t >> 3;                // 0..31, qt-descending order
            const int mt = (tq & 1) * 16 + (15 - (tq >> 1));
            const int m0 = mt * 128, n0 = nb * 128;

            if (tid == 0) {
                volatile int* p = &g_done[mt];
                while (*p < 16) __nanosleep(200);
            }
            __syncthreads();

            const fp16* Ah_ = g_AOh;
            const fp16* Bh_ = g_Wh + (size_t)3 * Dc * Dc;
            const int wr = wid >> 2, wc = wid & 3;

            auto issueG = [&](int c, int st) {
#pragma unroll
                for (int j = 0; j < 4; j++) {
                    const int tile = j >> 1;
                    const int idx = (j & 1) * 256 + tid;
                    const int row = idx >> 2, ch = idx & 3;
                    const fp16* g = (tile == 0)
                        ? Ah_ + (size_t)(m0 + row) * Dc + c * 32 + ch * 8
                        : Bh_ + (size_t)(n0 + row) * Dc + c * 32 + ch * 8;
                    cpa16(sb + (uint32_t)st * GT_STAGE +
                          (uint32_t)(tile * (int)GT_TILE + row * 80 + ch * 16), g);
                }
                cpa_commit();
            };

            float acc[4][4][4];
#pragma unroll
            for (int mtt = 0; mtt < 4; mtt++)
#pragma unroll
                for (int nt = 0; nt < 4; nt++)
#pragma unroll
                    for (int e = 0; e < 4; e++) acc[mtt][nt][e] = 0.f;

#pragma unroll
            for (int s = 0; s < GT_NST - 1; s++) issueG(s, s);

            for (int c = 0; c < 32; c++) {
                const int rem = 31 - c;
                if (rem >= GT_NST - 2)  { cpa_wait<GT_NST - 2>(); }
                else if (rem == 1)      { cpa_wait<1>(); }
                else                    { cpa_wait<0>(); }
                __syncthreads();
                if (c + GT_NST - 1 < 32) issueG(c + GT_NST - 1, (c + GT_NST - 1) & (GT_NST - 1));

                const uint32_t base = sb + (uint32_t)(c & (GT_NST - 1)) * GT_STAGE;
#pragma unroll
                for (int ks = 0; ks < 2; ks++) {
                    const uint32_t lk = (uint32_t)(ks * 16 + lko);
                    uint32_t af[4][4], bf2[2][4];
#pragma unroll
                    for (int mtt = 0; mtt < 4; mtt++) {
                        uint32_t ad = base + ((uint32_t)(wr * 64 + mtt * 16 + lrow) * 40u + lk) * 2u;
                        ldsm4(af[mtt], ad);
                    }
#pragma unroll
                    for (int nt2 = 0; nt2 < 2; nt2++) {
                        uint32_t bd = base + GT_TILE +
                                      ((uint32_t)(wc * 32 + nt2 * 16 + lrow) * 40u + lk) * 2u;
                        ldsm4(bf2[nt2], bd);
                    }
#pragma unroll
                    for (int mtt = 0; mtt < 4; mtt++)
#pragma unroll
                        for (int n8 = 0; n8 < 4; n8++) {
                            const int nt2 = n8 >> 1, sel = n8 & 1;
                            mma16816(acc[mtt][n8], af[mtt], bf2[nt2][sel], bf2[nt2][sel + 2]);
                        }
                }
            }

            // epilogue: fp32 out + bias
#pragma unroll
            for (int mtt = 0; mtt < 4; mtt++) {
#pragma unroll
                for (int nt = 0; nt < 4; nt++) {
                    int row = m0 + wr * 64 + mtt * 16 + gid;
                    int col = n0 + wc * 32 + nt * 8 + tig * 2;
                    float bx = bo[col], by = bo[col + 1];
                    *(float2*)(outf + (size_t)row * Dc + col) =
                        make_float2(acc[mtt][nt][0] + bx, acc[mtt][nt][1] + by);
                    *(float2*)(outf + (size_t)(row + 8) * Dc + col) =
                        make_float2(acc[mtt][nt][2] + bx, acc[mtt][nt][3] + by);
                }
            }
        }
    }
}

// ---------------------------------------------------------------------------
extern "C" void kernel_launch(void* const* d_in, const int* in_sizes, int n_in,
                              void* d_out, int out_size)
{
    const float* x  = (const float*)d_in[0];
    const float* Wq = (const float*)d_in[2];
    const float* bq = (const float*)d_in[3];
    const float* Wk = (const float*)d_in[4];
    const float* bk = (const float*)d_in[5];
    const float* Wv = (const float*)d_in[6];
    const float* bv = (const float*)d_in[7];
    const float* Wo = (const float*)d_in[8];
    const float* bo = (const float*)d_in[9];
    float* out = (float*)d_out;

    prep_kernel<<<dim3(32, 32, 5), dim3(32, 8)>>>(x, Wq, Wk, Wv, Wo);

    const int gsmem = GT_NST * GT_STAGE;  // 81920
    const int asmem = 5 * AT_TILE;        // 92160
    cudaFuncSetAttribute(gemm_qkv, cudaFuncAttributeMaxDynamicSharedMemorySize, gsmem);
    cudaFuncSetAttribute(fused_attn_out, cudaFuncAttributeMaxDynamicSharedMemorySize, asmem);

    gemm_qkv<<<dim3(24, 32), 256, gsmem>>>(bq, bk, bv);
    fused_attn_out<<<152, 256, asmem>>>(bo, out);
}

// round 16
// speedup vs baseline: 1.0266x; 1.0266x over previous
#include <cuda_runtime.h>
#include <cuda_fp16.h>
#include <cstdint>

#define Bc  2
#define Sc  2048
#define Dc  1024
#define Hc  16
#define DHc 64
#define Mrows (Bc*Sc)          // 4096
typedef __half fp16;

// ---------------- device scratch (no allocation allowed) ----------------
__device__ fp16 g_xh [Mrows*Dc];                        // x hi
__device__ fp16 g_Wh [4*Dc*Dc];                         // W^T hi, [n][k]
__device__ fp16 g_Qh [Bc*Hc*Sc*DHc];                    // Q hi (scale folded in)
__device__ fp16 g_Kh [Bc*Hc*Sc*DHc];                    // K hi
__device__ fp16 g_Vh [Bc*Hc*Sc*DHc];                    // V hi
__device__ fp16 g_AOh[Mrows*Dc];                        // AO hi
__device__ int  g_tick;

#define SCALE_L2E 0.18033688f   // 0.125 * log2(e), folded into Q

// ---------------- helpers ----------------
__device__ __forceinline__ uint32_t smem_u32(const void* p) {
    uint32_t a;
    asm("{ .reg .u64 t; cvta.to.shared.u64 t, %1; cvt.u32.u64 %0, t; }" : "=r"(a) : "l"(p));
    return a;
}
__device__ __forceinline__ void ldsm4(uint32_t* r, uint32_t addr) {
    asm volatile("ldmatrix.sync.aligned.m8n8.x4.shared.b16 {%0,%1,%2,%3}, [%4];"
        : "=r"(r[0]), "=r"(r[1]), "=r"(r[2]), "=r"(r[3]) : "r"(addr));
}
__device__ __forceinline__ void ldsm4t(uint32_t* r, uint32_t addr) {
    asm volatile("ldmatrix.sync.aligned.m8n8.x4.trans.shared.b16 {%0,%1,%2,%3}, [%4];"
        : "=r"(r[0]), "=r"(r[1]), "=r"(r[2]), "=r"(r[3]) : "r"(addr));
}
__device__ __forceinline__ void mma16816(float* d, const uint32_t* a,
                                         uint32_t b0, uint32_t b1) {
    asm volatile("mma.sync.aligned.m16n8k16.row.col.f32.f16.f16.f32 "
        "{%0,%1,%2,%3}, {%4,%5,%6,%7}, {%8,%9}, {%0,%1,%2,%3};"
        : "+f"(d[0]), "+f"(d[1]), "+f"(d[2]), "+f"(d[3])
        : "r"(a[0]), "r"(a[1]), "r"(a[2]), "r"(a[3]), "r"(b0), "r"(b1));
}
__device__ __forceinline__ uint32_t pack2h(float x, float y) {
    __half2 h = __floats2half2_rn(x, y);
    return *(uint32_t*)&h;
}
__device__ __forceinline__ float ex2f(float x) {
    float y;
    asm("ex2.approx.f32 %0, %1;" : "=f"(y) : "f"(x));
    return y;
}
__device__ __forceinline__ uint32_t hmax2(uint32_t a, uint32_t b) {
    uint32_t d;
    asm("max.f16x2 %0, %1, %2;" : "=r"(d) : "r"(a), "r"(b));
    return d;
}
__device__ __forceinline__ uint32_t hsub2(uint32_t a, uint32_t b) {
    uint32_t d;
    asm("sub.f16x2 %0, %1, %2;" : "=r"(d) : "r"(a), "r"(b));
    return d;
}
__device__ __forceinline__ uint32_t hex2(uint32_t a) {
    uint32_t d;
    asm("ex2.approx.f16x2 %0, %1;" : "=r"(d) : "r"(a));
    return d;
}
__device__ __forceinline__ void cpa16(uint32_t s, const void* g) {
    asm volatile("cp.async.cg.shared.global [%0], [%1], 16;" :: "r"(s), "l"(g));
}
__device__ __forceinline__ void cpa_commit() {
    asm volatile("cp.async.commit_group;" ::: "memory");
}
template<int N>
__device__ __forceinline__ void cpa_wait() {
    asm volatile("cp.async.wait_group %0;" :: "n"(N) : "memory");
}

// ---------------- prep: fused x-convert + 4 weight transposes ----------------
__global__ void prep_kernel(const float* __restrict__ x,
                            const float* __restrict__ Wq,
                            const float* __restrict__ Wk,
                            const float* __restrict__ Wv,
                            const float* __restrict__ Wo)
{
    if (blockIdx.z == 4) {
        const int blk = blockIdx.y * 32 + blockIdx.x;
        const int t = threadIdx.y * 32 + threadIdx.x;
        if (blk == 0 && t == 0) g_tick = 0;
        size_t i = ((size_t)blk * 256 + t) * 16;
#pragma unroll
        for (int j = 0; j < 2; j++) {
            float4 v0 = *(const float4*)(x + i + j * 8);
            float4 v1 = *(const float4*)(x + i + j * 8 + 4);
            uint4 o;
            o.x = pack2h(v0.x, v0.y); o.y = pack2h(v0.z, v0.w);
            o.z = pack2h(v1.x, v1.y); o.w = pack2h(v1.z, v1.w);
            *(uint4*)(g_xh + i + j * 8) = o;
        }
        return;
    }
    __shared__ float t[32][33];
    const int wsel = blockIdx.z;
    const float* src = (wsel == 0) ? Wq : (wsel == 1) ? Wk : (wsel == 2) ? Wv : Wo;
    fp16* dh = g_Wh + (size_t)wsel * Dc * Dc;
    int x0 = blockIdx.x * 32 + threadIdx.x;
    int y0 = blockIdx.y * 32 + threadIdx.y;
#pragma unroll
    for (int i = 0; i < 32; i += 8) t[threadIdx.y + i][threadIdx.x] = src[(y0 + i) * Dc + x0];
    __syncthreads();
    x0 = blockIdx.y * 32 + threadIdx.x;
    y0 = blockIdx.x * 32 + threadIdx.y;
#pragma unroll
    for (int i = 0; i < 32; i += 8)
        dh[(size_t)(y0 + i) * Dc + x0] = __float2half_rn(t[threadIdx.x][threadIdx.y + i]);
}

// ---------------------------------------------------------------------------
// fp16 1-term GEMM, tile 128x128, BK=32, 256 thr (8 warps 2x4),
// cp.async 4-stage x 2-tile pipeline, 2 CTAs/SM.
// MODE 1 (QKV, grid.x=24): C = xh @ Wh + bias -> head layout (Q *SCALE_L2E).
// MODE 0 (out, grid.x=8):  C = AOh @ Wo_h + bo -> fp32 out.
// ---------------------------------------------------------------------------
#define GT_TILE  10240u    // 128*40*2
#define GT_STAGE 20480u    // 2 tiles
#define GT_NST   4

template <int MODE>
__global__ __launch_bounds__(256, 2)
void gemm_mma(const float* __restrict__ b0, const float* __restrict__ b1,
              const float* __restrict__ b2, float* __restrict__ outf)
{
    extern __shared__ unsigned char smraw[];
    const uint32_t sb = smem_u32(smraw);
    const int tid = threadIdx.x;
    const int wid = tid >> 5, lid = tid & 31;
    const int wr = wid >> 2, wc = wid & 3;
    const int m0 = blockIdx.y * 128;

    int wsel, n0;
    const fp16 *Ah_, *Bh_;
    const float* bias;
    if (MODE == 1) {
        wsel = blockIdx.x >> 3; n0 = (blockIdx.x & 7) * 128;
        Ah_ = g_xh;
        Bh_ = g_Wh + (size_t)wsel * Dc * Dc;
        bias = (wsel == 0) ? b0 : (wsel == 1) ? b1 : b2;
    } else {
        wsel = 3; n0 = blockIdx.x * 128;
        Ah_ = g_AOh;
        Bh_ = g_Wh + (size_t)3 * Dc * Dc;
        bias = b0;
    }

    auto issue = [&](int c, int st) {
#pragma unroll
        for (int j = 0; j < 4; j++) {
            const int tile = j >> 1;                 // 0 A, 1 B
            const int idx = (j & 1) * 256 + tid;     // 0..511
            const int row = idx >> 2, ch = idx & 3;
            const fp16* g = (tile == 0)
                ? Ah_ + (size_t)(m0 + row) * Dc + c * 32 + ch * 8
                : Bh_ + (size_t)(n0 + row) * Dc + c * 32 + ch * 8;
            cpa16(sb + (uint32_t)st * GT_STAGE +
                  (uint32_t)(tile * (int)GT_TILE + row * 80 + ch * 16), g);
        }
        cpa_commit();
    };

    float acc[4][4][4];
#pragma unroll
    for (int mt = 0; mt < 4; mt++)
#pragma unroll
        for (int nt = 0; nt < 4; nt++)
#pragma unroll
            for (int e = 0; e < 4; e++) acc[mt][nt][e] = 0.f;

#pragma unroll
    for (int s = 0; s < GT_NST - 1; s++) issue(s, s);

    const int lrow = lid & 15;
    const int lko  = (lid >> 4) << 3;

    for (int c = 0; c < 32; c++) {
        const int rem = 31 - c;
        if (rem >= GT_NST - 2)  { cpa_wait<GT_NST - 2>(); }
        else if (rem == 1)      { cpa_wait<1>(); }
        else                    { cpa_wait<0>(); }
        __syncthreads();
        if (c + GT_NST - 1 < 32) issue(c + GT_NST - 1, (c + GT_NST - 1) & (GT_NST - 1));

        const uint32_t base = sb + (uint32_t)(c & (GT_NST - 1)) * GT_STAGE;
#pragma unroll
        for (int ks = 0; ks < 2; ks++) {
            const uint32_t lk = (uint32_t)(ks * 16 + lko);
            uint32_t af[4][4], bf2[2][4];
#pragma unroll
            for (int mt = 0; mt < 4; mt++) {
                uint32_t ad = base + ((uint32_t)(wr * 64 + mt * 16 + lrow) * 40u + lk) * 2u;
                ldsm4(af[mt], ad);
            }
#pragma unroll
            for (int nt2 = 0; nt2 < 2; nt2++) {
                uint32_t bd = base + GT_TILE +
                              ((uint32_t)(wc * 32 + nt2 * 16 + lrow) * 40u + lk) * 2u;
                ldsm4(bf2[nt2], bd);
            }
#pragma unroll
            for (int mt = 0; mt < 4; mt++)
#pragma unroll
                for (int n8 = 0; n8 < 4; n8++) {
                    const int nt2 = n8 >> 1, sel = n8 & 1;
                    mma16816(acc[mt][n8], af[mt], bf2[nt2][sel], bf2[nt2][sel + 2]);
                }
        }
    }

    // epilogue
    const int gid = lid >> 2, tig = lid & 3;
#pragma unroll
    for (int mt = 0; mt < 4; mt++) {
#pragma unroll
        for (int nt = 0; nt < 4; nt++) {
            int row = m0 + wr * 64 + mt * 16 + gid;
            int col = n0 + wc * 32 + nt * 8 + tig * 2;
            float bx = bias[col], by = bias[col + 1];
            float v00 = acc[mt][nt][0] + bx, v01 = acc[mt][nt][1] + by;
            float v10 = acc[mt][nt][2] + bx, v11 = acc[mt][nt][3] + by;
            if (MODE == 0) {
                *(float2*)(outf + (size_t)row * Dc + col) = make_float2(v00, v01);
                *(float2*)(outf + (size_t)(row + 8) * Dc + col) = make_float2(v10, v11);
            } else {
                int h = col >> 6, dh = col & 63;
                int bb = row >> 11, s = row & (Sc - 1);
                size_t p0 = ((size_t)(bb * Hc + h) * Sc + s) * DHc + dh;
                size_t p1 = ((size_t)(bb * Hc + h) * Sc + (s + 8)) * DHc + dh;
                if (wsel == 0) {        // Q: fold softmax scale
                    *(uint32_t*)(g_Qh + p0) = pack2h(v00 * SCALE_L2E, v01 * SCALE_L2E);
                    *(uint32_t*)(g_Qh + p1) = pack2h(v10 * SCALE_L2E, v11 * SCALE_L2E);
                } else {
                    fp16* Oh = (wsel == 1) ? g_Kh : g_Vh;
                    *(uint32_t*)(Oh + p0) = pack2h(v00, v01);
                    *(uint32_t*)(Oh + p1) = pack2h(v10, v11);
                }
            }
        }
    }
}

// ---------------------------------------------------------------------------
// Persistent ticket-scheduled flash attention (fp16 mma, 1-term).
// S = qh @ kh^T (scale pre-folded); f16x2 softmax; row sums via ones MMA;
// PV 1-term. Diagonal k-tile: fully-masked MMA blocks skipped (exact).
// 256 thr, 1 CTA/SM, LPT. smem: 2x{Kh,Vh} + Q = 5 tiles = 92160B.
// ---------------------------------------------------------------------------
#define AT_STRIDE 72u
#define AT_TILE   18432u   // 128*72*2
#define N_ITEMS   512      // 16 qt * 32 bh

__global__ __launch_bounds__(256, 1)
void attn_mma()
{
    extern __shared__ unsigned char smraw[];
    __shared__ int s_item;
    const uint32_t sb = smem_u32(smraw);

    const int tid = threadIdx.x;
    const int wid = tid >> 5, lid = tid & 31;
    const int gid = lid >> 2, tig = lid & 3;
    const int lrow = lid & 15, lko = (lid >> 4) << 3;
    const uint32_t s_one = (lid < 4) ? 0x3C003C00u : 0u;   // ones col-0 B frag

    for (;;) {
        if (tid == 0) s_item = atomicAdd(&g_tick, 1);
        __syncthreads();
        const int item = s_item;
        if (item >= N_ITEMS) return;

        const int qt = 15 - (item >> 5);     // heavy first (LPT)
        const int bh = item & 31;
        const int q0 = qt * 128;
        const size_t hb = (size_t)bh * (Sc * DHc);

        auto issue_kv = [&](int kt, int buf) {
            const uint32_t bbase = sb + (uint32_t)buf * (2u * AT_TILE);
            const int k0 = kt * 128;
#pragma unroll
            for (int j = 0; j < 8; j++) {
                const int tile = j >> 2;          // 0 Kh, 1 Vh
                const int idx = (j & 3) * 256 + tid;
                const int row = idx >> 3, ch = idx & 7;
                const fp16* g = (tile == 0 ? g_Kh : g_Vh) + hb +
                                (size_t)(k0 + row) * DHc + ch * 8;
                cpa16(bbase + (uint32_t)(tile * (int)AT_TILE + row * 144 + ch * 16), g);
            }
            cpa_commit();
        };

        // --- stage Q (group 1), then prefetch KV tile 0 (group 2) ---
#pragma unroll
        for (int j = 0; j < 4; j++) {
            const int idx = j * 256 + tid;        // 0..1023
            const int row = idx >> 3, ch = idx & 7;
            const fp16* g = g_Qh + hb + (size_t)(q0 + row) * DHc + ch * 8;
            cpa16(sb + (uint32_t)(4 * (int)AT_TILE + row * 144 + ch * 16), g);
        }
        cpa_commit();
        issue_kv(0, 0);
        cpa_wait<1>();                            // Q ready (KV0 may be in flight)
        __syncthreads();

        uint32_t qh[4][4];
#pragma unroll
        for (int ks = 0; ks < 4; ks++) {
            uint32_t ad = sb + 4u * AT_TILE + ((uint32_t)(wid * 16 + lrow) * AT_STRIDE +
                                               (uint32_t)(ks * 16 + lko)) * 2u;
            ldsm4(qh[ks], ad);
        }

        float m_i[2] = {-1e30f, -1e30f}, l_i[2] = {0.f, 0.f};
        float oacc[8][4];
#pragma unroll
        for (int n8 = 0; n8 < 8; n8++)
#pragma unroll
            for (int e = 0; e < 4; e++) oacc[n8][e] = 0.f;

        for (int kt = 0; kt <= qt; kt++) {
            cpa_wait<0>();
            __syncthreads();
            if (kt < qt) issue_kv(kt + 1, (kt + 1) & 1);

            const uint32_t bbuf = sb + (uint32_t)(kt & 1) * (2u * AT_TILE);
            const bool diag = (kt == qt);

            // --- S = Q K^T (1-term; skip fully-masked diagonal blocks) ---
            float sacc[16][4];
#pragma unroll
            for (int j = 0; j < 16; j++)
#pragma unroll
                for (int e = 0; e < 4; e++) sacc[j][e] = 0.f;

#pragma unroll
            for (int nt2 = 0; nt2 < 8; nt2++) {
                if (diag && nt2 > wid) continue;   // cols entirely > rows: masked
#pragma unroll
                for (int ks = 0; ks < 4; ks++) {
                    uint32_t bh4[4];
                    uint32_t bd = bbuf + ((uint32_t)(nt2 * 16 + lrow) * AT_STRIDE +
                                          (uint32_t)(ks * 16 + lko)) * 2u;
                    ldsm4(bh4, bd);
#pragma unroll
                    for (int sel = 0; sel < 2; sel++)
                        mma16816(sacc[nt2 * 2 + sel], qh[ks], bh4[sel], bh4[sel + 2]);
                }
            }

            // --- causal mask on diagonal tile only ---
            if (diag) {
#pragma unroll
                for (int j = 0; j < 16; j++)
#pragma unroll
                    for (int e = 0; e < 4; e++) {
                        int row = wid * 16 + gid + ((e >> 1) << 3);
                        int col = j * 8 + tig * 2 + (e & 1);
                        if (col > row) sacc[j][e] = -1e30f;
                    }
            }

            // --- pack to half2: h0 = rows gid, h1 = rows gid+8 ---
            uint32_t h0[16], h1[16];
#pragma unroll
            for (int j = 0; j < 16; j++) {
                h0[j] = pack2h(sacc[j][0], sacc[j][1]);
                h1[j] = pack2h(sacc[j][2], sacc[j][3]);
            }

            // --- fp16 online softmax (exp2 domain), rs via ones-MMA ---
            float corr[2];
#pragma unroll
            for (int hrow = 0; hrow < 2; hrow++) {
                uint32_t* hx = hrow ? h1 : h0;
                uint32_t m2 = hx[0];
#pragma unroll
                for (int j = 1; j < 16; j++) m2 = hmax2(m2, hx[j]);
                __half2 hm = *(__half2*)&m2;
                float mxf = fmaxf(__half2float(__low2half(hm)),
                                  __half2float(__high2half(hm)));
                mxf = fmaxf(mxf, __shfl_xor_sync(0xffffffffu, mxf, 1));
                mxf = fmaxf(mxf, __shfl_xor_sync(0xffffffffu, mxf, 2));
                float mnew = fmaxf(m_i[hrow], mxf);
                corr[hrow] = ex2f(m_i[hrow] - mnew);
                m_i[hrow] = mnew;
                const uint32_t mn2 = pack2h(mnew, mnew);
#pragma unroll
                for (int j = 0; j < 16; j++) hx[j] = hex2(hsub2(hx[j], mn2));
                const int e0 = hrow * 2;
#pragma unroll
                for (int n8 = 0; n8 < 8; n8++) {
                    oacc[n8][e0]     *= corr[hrow];
                    oacc[n8][e0 + 1] *= corr[hrow];
                }
            }

            // --- O += P V (1-term) + row sums; skip all-zero diagonal blocks ---
            float lacc[4] = {0.f, 0.f, 0.f, 0.f};
#pragma unroll
            for (int ks2 = 0; ks2 < 8; ks2++) {
                if (diag && ks2 > wid) continue;   // P cols here are exactly 0
                uint32_t pa[4];
                pa[0] = h0[2 * ks2];     pa[1] = h1[2 * ks2];
                pa[2] = h0[2 * ks2 + 1]; pa[3] = h1[2 * ks2 + 1];

                mma16816(lacc, pa, s_one, s_one);

                const int mat = lid >> 3, rin = lid & 7;
                const uint32_t vrow = (uint32_t)(ks2 * 16 + (mat & 1) * 8 + rin);
#pragma unroll
                for (int n2 = 0; n2 < 4; n2++) {
                    uint32_t vh4[4];
                    uint32_t vd = bbuf + AT_TILE +
                                  (vrow * AT_STRIDE + (uint32_t)(n2 * 16 + (mat >> 1) * 8)) * 2u;
                    ldsm4t(vh4, vd);
#pragma unroll
                    for (int sel = 0; sel < 2; sel++)
                        mma16816(oacc[n2 * 2 + sel], pa, vh4[sel * 2], vh4[sel * 2 + 1]);
                }
            }

            const int src = (lid >> 2) << 2;
            float rs0 = __shfl_sync(0xffffffffu, lacc[0], src);
            float rs1 = __shfl_sync(0xffffffffu, lacc[2], src);
            l_i[0] = l_i[0] * corr[0] + rs0;
            l_i[1] = l_i[1] * corr[1] + rs1;
        }

        // --- epilogue: normalize + write AO hi (fp16) ---
        const int b = bh >> 4, h = bh & 15;
        const float inv0 = 1.f / l_i[0], inv1 = 1.f / l_i[1];
        const int row0 = q0 + wid * 16 + gid;
#pragma unroll
        for (int n8 = 0; n8 < 8; n8++) {
            const int col = h * DHc + n8 * 8 + tig * 2;
            size_t p0 = ((size_t)b * Sc + row0) * Dc + col;
            size_t p1 = ((size_t)b * Sc + row0 + 8) * Dc + col;
            *(uint32_t*)(g_AOh + p0) = pack2h(oacc[n8][0] * inv0, oacc[n8][1] * inv0);
            *(uint32_t*)(g_AOh + p1) = pack2h(oacc[n8][2] * inv1, oacc[n8][3] * inv1);
        }
    }
}

// ---------------------------------------------------------------------------
extern "C" void kernel_launch(void* const* d_in, const int* in_sizes, int n_in,
                              void* d_out, int out_size)
{
    const float* x  = (const float*)d_in[0];
    const float* Wq = (const float*)d_in[2];
    const float* bq = (const float*)d_in[3];
    const float* Wk = (const float*)d_in[4];
    const float* bk = (const float*)d_in[5];
    const float* Wv = (const float*)d_in[6];
    const float* bv = (const float*)d_in[7];
    const float* Wo = (const float*)d_in[8];
    const float* bo = (const float*)d_in[9];
    float* out = (float*)d_out;

    prep_kernel<<<dim3(32, 32, 5), dim3(32, 8)>>>(x, Wq, Wk, Wv, Wo);

    const int gsmem = GT_NST * GT_STAGE;  // 81920
    const int asmem = 5 * AT_TILE;        // 92160
    cudaFuncSetAttribute(gemm_mma<1>, cudaFuncAttributeMaxDynamicSharedMemorySize, gsmem);
    cudaFuncSetAttribute(gemm_mma<0>, cudaFuncAttributeMaxDynamicSharedMemorySize, gsmem);
    cudaFuncSetAttribute(attn_mma, cudaFuncAttributeMaxDynamicSharedMemorySize, asmem);

    gemm_mma<1><<<dim3(24, 32), 256, gsmem>>>(bq, bk, bv, nullptr);
    attn_mma<<<152, 256, asmem>>>();
    gemm_mma<0><<<dim3(8, 32), 256, gsmem>>>(bo, nullptr, nullptr, out);
}